// round 1
// baseline (speedup 1.0000x reference)
#include <cuda_runtime.h>

#define BB 2
#define HH 512
#define WW 512
#define HW (HH*WW)          // 262144
#define CC 256
#define CHW ((size_t)CC*HW)
#define NPIX (BB*HW)        // 524288

// ---------------- device scratch (static, no allocation) ----------------
__device__ uchar4        g_img[NPIX];          // normalized pseudo-RGB, 2 MB
__device__ unsigned char g_alpha[2][NPIX];     // ping-pong alpha, 1 MB
__device__ unsigned int  g_mn[BB], g_mx[BB];   // order-mapped min/max
__device__ double        g_fgsum[6][BB][3];    // fg color sums per iteration
__device__ float         g_fgcnt[6][BB];       // fg counts per iteration
__device__ double        g_tot[BB][3];         // total color sums (constant)

// monotonic float<->uint order mapping for atomicMin/Max
__device__ __forceinline__ unsigned f2ord(float f) {
    unsigned u = __float_as_uint(f);
    return (u & 0x80000000u) ? ~u : (u | 0x80000000u);
}
__device__ __forceinline__ float ord2f(unsigned u) {
    unsigned bits = (u & 0x80000000u) ? (u ^ 0x80000000u) : ~u;
    return __uint_as_float(bits);
}

// normalization exactly as reference: clip(floor((f-mn)/(mx-mn+1e-12)*255),0,255)
__device__ __forceinline__ float normq(float f, float mn, float den) {
    float v = __fmul_rn(__fdiv_rn(__fsub_rn(f, mn), den), 255.0f);
    v = floorf(v);
    return fminf(fmaxf(v, 0.0f), 255.0f);
}

// trimap geometry: bh=bw=int(512*0.1)=51; center rows/cols [230,281)
__device__ __forceinline__ bool is_border(int y, int x) {
    return (y < 51) | (y >= 461) | (x < 51) | (x >= 461);
}
__device__ __forceinline__ bool is_center(int y, int x) {
    return (y >= 230) & (y < 281) & (x >= 230) & (x < 281);
}

// ---------------- kernel 0: zero accumulators ----------------
__global__ void k_init() {
    int t = threadIdx.x;
    if (t < 6 * BB * 3) ((double*)g_fgsum)[t] = 0.0;
    if (t < 6 * BB)     ((float*)g_fgcnt)[t] = 0.0f;
    if (t < BB * 3)     ((double*)g_tot)[t] = 0.0;
    if (t < BB) { g_mn[t] = 0xFFFFFFFFu; g_mx[t] = 0u; }
}

// ---------------- kernel 1: per-batch min/max over first 3 channels ----------------
__global__ void k_minmax(const float* __restrict__ feat) {
    int b = blockIdx.y;
    const float4* src = (const float4*)(feat + (size_t)b * CHW);
    const int n4 = 3 * HW / 4;
    unsigned mn = 0xFFFFFFFFu, mx = 0u;
    for (int i = blockIdx.x * blockDim.x + threadIdx.x; i < n4;
         i += gridDim.x * blockDim.x) {
        float4 v = src[i];
        unsigned u;
        u = f2ord(v.x); mn = min(mn, u); mx = max(mx, u);
        u = f2ord(v.y); mn = min(mn, u); mx = max(mx, u);
        u = f2ord(v.z); mn = min(mn, u); mx = max(mx, u);
        u = f2ord(v.w); mn = min(mn, u); mx = max(mx, u);
    }
    #pragma unroll
    for (int o = 16; o; o >>= 1) {
        mn = min(mn, __shfl_down_sync(0xFFFFFFFFu, mn, o));
        mx = max(mx, __shfl_down_sync(0xFFFFFFFFu, mx, o));
    }
    __shared__ unsigned smn[8], smx[8];
    int w = threadIdx.x >> 5;
    if ((threadIdx.x & 31) == 0) { smn[w] = mn; smx[w] = mx; }
    __syncthreads();
    if (threadIdx.x == 0) {
        int nw = blockDim.x >> 5;
        for (int i = 1; i < nw; i++) { mn = min(mn, smn[i]); mx = max(mx, smx[i]); }
        atomicMin(&g_mn[b], mn);
        atomicMax(&g_mx[b], mx);
    }
}

// ---------------- kernel 2: normalize + trimap + alpha0 + sums ----------------
__global__ void k_prep(const float* __restrict__ feat, const int* __restrict__ mask) {
    int blk = blockIdx.x;               // 512 blocks x 1024 contiguous pixels
    int t = threadIdx.x;
    int p0 = blk * 1024;
    int b = p0 >> 18;                   // p0 / HW — block never straddles batches
    float mnf = ord2f(g_mn[b]);
    float mxf = ord2f(g_mx[b]);
    float den = __fadd_rn(__fsub_rn(mxf, mnf), 1e-12f);
    const float* fb = feat + (size_t)b * CHW;

    float s0 = 0, s1 = 0, s2 = 0, cnt = 0, t0 = 0, t1 = 0, t2 = 0;
    #pragma unroll
    for (int k = 0; k < 4; k++) {
        int p = p0 + k * 256 + t;
        int r = p & (HW - 1);
        int y = r >> 9, x = r & 511;
        float q0 = normq(fb[r],            mnf, den);
        float q1 = normq(fb[HW + r],       mnf, den);
        float q2 = normq(fb[2 * HW + r],   mnf, den);
        bool border = is_border(y, x);
        bool center = is_center(y, x);
        unsigned char a = border ? 0 : (center ? 1 : (mask[p] == 1 ? 1 : 0));
        g_img[p] = make_uchar4((unsigned char)q0, (unsigned char)q1,
                               (unsigned char)q2, 0);
        g_alpha[0][p] = a;
        float af = (float)a;
        s0 += q0 * af; s1 += q1 * af; s2 += q2 * af; cnt += af;
        t0 += q0; t1 += q1; t2 += q2;
    }
    __shared__ float red[7][256];
    red[0][t] = s0; red[1][t] = s1; red[2][t] = s2; red[3][t] = cnt;
    red[4][t] = t0; red[5][t] = t1; red[6][t] = t2;
    __syncthreads();
    for (int s = 128; s > 0; s >>= 1) {
        if (t < s) {
            #pragma unroll
            for (int j = 0; j < 7; j++) red[j][t] += red[j][t + s];
        }
        __syncthreads();
    }
    if (t == 0) {
        atomicAdd(&g_fgsum[0][b][0], (double)red[0][0]);
        atomicAdd(&g_fgsum[0][b][1], (double)red[1][0]);
        atomicAdd(&g_fgsum[0][b][2], (double)red[2][0]);
        atomicAdd(&g_fgcnt[0][b], red[3][0]);
        atomicAdd(&g_tot[b][0], (double)red[4][0]);
        atomicAdd(&g_tot[b][1], (double)red[5][0]);
        atomicAdd(&g_tot[b][2], (double)red[6][0]);
    }
}

// ---------------- kernels 3..7: one ICM iteration (relabel + next-iter sums) ----------------
__global__ void k_iter(float* __restrict__ out, int k, int last) {
    int blk = blockIdx.x;
    int t = threadIdx.x;
    int p0 = blk * 1024;
    int b = p0 >> 18;

    // means (exact integer sums in double -> correctly rounded float, fp32 divide)
    float cntf = g_fgcnt[k][b];
    float fgc = __fadd_rn(cntf, 1e-6f);
    float bgc = __fadd_rn(__fsub_rn((float)HW, cntf), 1e-6f);
    float fm0 = __fdiv_rn((float)g_fgsum[k][b][0], fgc);
    float fm1 = __fdiv_rn((float)g_fgsum[k][b][1], fgc);
    float fm2 = __fdiv_rn((float)g_fgsum[k][b][2], fgc);
    float bm0 = __fdiv_rn((float)(g_tot[b][0] - g_fgsum[k][b][0]), bgc);
    float bm1 = __fdiv_rn((float)(g_tot[b][1] - g_fgsum[k][b][1]), bgc);
    float bm2 = __fdiv_rn((float)(g_tot[b][2] - g_fgsum[k][b][2]), bgc);

    const unsigned char* __restrict__ A = g_alpha[k & 1];
    unsigned char* __restrict__ An = g_alpha[(k + 1) & 1];

    float s0 = 0, s1 = 0, s2 = 0, cnt = 0;
    #pragma unroll
    for (int kk = 0; kk < 4; kk++) {
        int p = p0 + kk * 256 + t;
        int r = p & (HW - 1);
        int y = r >> 9, x = r & 511;
        uchar4 q = g_img[p];
        float i0 = (float)q.x, i1 = (float)q.y, i2 = (float)q.z;

        int up = (y > 0)      ? p - WW : p;
        int dn = (y < HH - 1) ? p + WW : p;
        int lf = (x > 0)      ? p - 1  : p;
        int rt = (x < WW - 1) ? p + 1  : p;
        float nb = __fmul_rn((float)((int)A[up] + (int)A[dn] + (int)A[lf] + (int)A[rt]),
                             0.25f);

        float d0 = __fsub_rn(i0, fm0), d1 = __fsub_rn(i1, fm1), d2 = __fsub_rn(i2, fm2);
        float dfg = __fadd_rn(__fadd_rn(__fmul_rn(d0, d0), __fmul_rn(d1, d1)),
                              __fmul_rn(d2, d2));
        float e0 = __fsub_rn(i0, bm0), e1 = __fsub_rn(i1, bm1), e2 = __fsub_rn(i2, bm2);
        float dbg = __fadd_rn(__fadd_rn(__fmul_rn(e0, e0), __fmul_rn(e1, e1)),
                              __fmul_rn(e2, e2));

        float pw = __fmul_rn(50.0f, __fsub_rn(__fmul_rn(2.0f, nb), 1.0f));
        float score = __fadd_rn(__fsub_rn(dbg, dfg), pw);

        bool border = is_border(y, x);
        bool center = is_center(y, x);
        unsigned char a = (border | center) ? (center ? 1 : 0)
                                            : (score > 0.0f ? 1 : 0);
        An[p] = a;
        if (last) out[p] = (float)a;
        float af = (float)a;
        s0 += i0 * af; s1 += i1 * af; s2 += i2 * af; cnt += af;
    }

    if (!last) {
        __shared__ float red[4][256];
        red[0][t] = s0; red[1][t] = s1; red[2][t] = s2; red[3][t] = cnt;
        __syncthreads();
        for (int s = 128; s > 0; s >>= 1) {
            if (t < s) {
                #pragma unroll
                for (int j = 0; j < 4; j++) red[j][t] += red[j][t + s];
            }
            __syncthreads();
        }
        if (t == 0) {
            atomicAdd(&g_fgsum[k + 1][b][0], (double)red[0][0]);
            atomicAdd(&g_fgsum[k + 1][b][1], (double)red[1][0]);
            atomicAdd(&g_fgsum[k + 1][b][2], (double)red[2][0]);
            atomicAdd(&g_fgcnt[k + 1][b], red[3][0]);
        }
    }
}

extern "C" void kernel_launch(void* const* d_in, const int* in_sizes, int n_in,
                              void* d_out, int out_size) {
    const float* feat = (const float*)d_in[0];
    const int*   mask = (const int*)d_in[1];
    float*       out  = (float*)d_out;

    k_init<<<1, 64>>>();
    k_minmax<<<dim3(96, 2), 256>>>(feat);
    k_prep<<<512, 256>>>(feat, mask);
    for (int k = 0; k < 5; k++)
        k_iter<<<512, 256>>>(out, k, (k == 4) ? 1 : 0);
}

// round 2
// speedup vs baseline: 1.5719x; 1.5719x over previous
#include <cuda_runtime.h>

#define BB 2
#define HH 512
#define WW 512
#define HW (HH*WW)            // 262144
#define CHW ((size_t)256*HW)
#define NPIX (BB*HW)          // 524288
#define GRID 256
#define TPB 256
#define NTH (GRID*TPB)        // 65536 threads, 8 px each

// ---------------- device scratch (static, no allocation) ----------------
__device__ uchar4        g_img[NPIX];          // normalized pseudo-RGB, 2 MB
__device__ unsigned char g_alpha[2][NPIX];     // ping-pong alpha, 1 MB
__device__ unsigned int  g_mn[BB], g_mx[BB];   // order-mapped min/max
__device__ double        g_fgsum[6][BB][3];    // fg color sums per iteration
__device__ float         g_fgcnt[6][BB];       // fg counts per iteration
__device__ double        g_tot[BB][3];         // total color sums (constant)
__device__ unsigned int  g_barcnt;             // grid barrier counter

__device__ __forceinline__ unsigned f2ord(float f) {
    unsigned u = __float_as_uint(f);
    return (u & 0x80000000u) ? ~u : (u | 0x80000000u);
}
__device__ __forceinline__ float ord2f(unsigned u) {
    return __uint_as_float((u & 0x80000000u) ? (u ^ 0x80000000u) : ~u);
}
__device__ __forceinline__ float normq(float f, float mn, float den) {
    float v = __fmul_rn(__fdiv_rn(__fsub_rn(f, mn), den), 255.0f);
    v = floorf(v);
    return fminf(fmaxf(v, 0.0f), 255.0f);
}

// software grid barrier: all 256 blocks resident by construction
__device__ __forceinline__ void gridbar(unsigned target) {
    __threadfence();           // make this thread's stores L2-visible
    __syncthreads();           // whole block's fences done
    if (threadIdx.x == 0) {
        unsigned a = atomicAdd(&g_barcnt, 1u) + 1u;
        if (a < target)
            while (*(volatile unsigned*)&g_barcnt < target) { __nanosleep(32); }
    }
    __syncthreads();
}

// ---------------- kernel 0: zero accumulators + barrier counter ----------------
__global__ void k_init() {
    int t = threadIdx.x;
    if (t < 36) ((double*)g_fgsum)[t] = 0.0;
    if (t < 12) ((float*)g_fgcnt)[t] = 0.0f;
    if (t < 6)  ((double*)g_tot)[t] = 0.0;
    if (t < BB) { g_mn[t] = 0xFFFFFFFFu; g_mx[t] = 0u; }
    if (t == 0) g_barcnt = 0u;
}

// ---------------- the whole pipeline, one persistent kernel ----------------
__global__ void __launch_bounds__(TPB, 2)
k_fused(const float* __restrict__ feat, const int* __restrict__ mask,
        float* __restrict__ out) {
    const int t    = threadIdx.x;
    const int tid  = blockIdx.x * TPB + t;
    const int lane = t & 31, warp = t >> 5;
    unsigned bar = 0;

    __shared__ unsigned s_u[16];
    __shared__ float    s_f[7 * 8];
    __shared__ float    s_means[8];

    // ======== phase 1: per-batch min/max over first 3 channels ========
    #pragma unroll
    for (int b = 0; b < BB; b++) {
        const float4* s = (const float4*)(feat + (size_t)b * CHW);
        unsigned mn = 0xFFFFFFFFu, mx = 0u;
        #pragma unroll
        for (int it = 0; it < 3; it++) {            // 3*HW/4 = 3*NTH float4
            float4 v = s[tid + it * NTH];
            unsigned u;
            u = f2ord(v.x); mn = min(mn, u); mx = max(mx, u);
            u = f2ord(v.y); mn = min(mn, u); mx = max(mx, u);
            u = f2ord(v.z); mn = min(mn, u); mx = max(mx, u);
            u = f2ord(v.w); mn = min(mn, u); mx = max(mx, u);
        }
        #pragma unroll
        for (int o = 16; o; o >>= 1) {
            mn = min(mn, __shfl_down_sync(0xFFFFFFFFu, mn, o));
            mx = max(mx, __shfl_down_sync(0xFFFFFFFFu, mx, o));
        }
        if (lane == 0) { s_u[warp] = mn; s_u[8 + warp] = mx; }
        __syncthreads();
        if (t == 0) {
            for (int i = 1; i < 8; i++) { mn = min(mn, s_u[i]); mx = max(mx, s_u[8 + i]); }
            atomicMin(&g_mn[b], mn);
            atomicMax(&g_mx[b], mx);
        }
        __syncthreads();
    }
    bar += GRID; gridbar(bar);

    // fixed geometry for this thread's 8 pixels
    const int p0 = tid * 8;
    const int b  = p0 >> 18;
    const int r  = p0 & (HW - 1);
    const int y  = r >> 9;
    const int x0 = r & 511;
    const bool yb = (y < 51) | (y >= 461);
    const bool yc = (y >= 230) & (y < 281);
    unsigned char fixedv[8], fixval[8];
    #pragma unroll
    for (int j = 0; j < 8; j++) {
        int xj = x0 + j;
        bool border = yb | (xj < 51) | (xj >= 461);
        bool center = yc & (xj >= 230) & (xj < 281);
        fixedv[j] = border | center;
        fixval[j] = center ? 1 : 0;
    }

    // ======== phase 2: normalize + trimap + alpha0 + exact sums ========
    {
        if (t == 0) {
            float mnf = ord2f(__ldcg(&g_mn[b]));
            float mxf = ord2f(__ldcg(&g_mx[b]));
            s_means[0] = mnf;
            s_means[1] = __fadd_rn(__fsub_rn(mxf, mnf), 1e-12f);
        }
        __syncthreads();
        float mnf = s_means[0], den = s_means[1];
        const float* fb = feat + (size_t)b * CHW;
        float4 c0a = *(const float4*)(fb + r),          c0b = *(const float4*)(fb + r + 4);
        float4 c1a = *(const float4*)(fb + HW + r),     c1b = *(const float4*)(fb + HW + r + 4);
        float4 c2a = *(const float4*)(fb + 2*HW + r),   c2b = *(const float4*)(fb + 2*HW + r + 4);
        int4 m0 = *(const int4*)(mask + p0), m1 = *(const int4*)(mask + p0 + 4);
        float f0[8] = {c0a.x,c0a.y,c0a.z,c0a.w,c0b.x,c0b.y,c0b.z,c0b.w};
        float f1[8] = {c1a.x,c1a.y,c1a.z,c1a.w,c1b.x,c1b.y,c1b.z,c1b.w};
        float f2[8] = {c2a.x,c2a.y,c2a.z,c2a.w,c2b.x,c2b.y,c2b.z,c2b.w};
        int   mk[8] = {m0.x,m0.y,m0.z,m0.w,m1.x,m1.y,m1.z,m1.w};

        unsigned imgpack[8]; unsigned av[8];
        float s0=0,s1=0,s2=0,cnt=0,t0=0,t1=0,t2=0;
        #pragma unroll
        for (int j = 0; j < 8; j++) {
            float q0 = normq(f0[j], mnf, den);
            float q1 = normq(f1[j], mnf, den);
            float q2 = normq(f2[j], mnf, den);
            unsigned a = fixedv[j] ? (unsigned)fixval[j] : (mk[j] == 1 ? 1u : 0u);
            imgpack[j] = (unsigned)q0 | ((unsigned)q1 << 8) | ((unsigned)q2 << 16);
            av[j] = a;
            float af = (float)a;
            s0 += q0*af; s1 += q1*af; s2 += q2*af; cnt += af;
            t0 += q0; t1 += q1; t2 += q2;
        }
        *(uint4*)&g_img[p0]     = make_uint4(imgpack[0],imgpack[1],imgpack[2],imgpack[3]);
        *(uint4*)&g_img[p0 + 4] = make_uint4(imgpack[4],imgpack[5],imgpack[6],imgpack[7]);
        unsigned lo = av[0] | (av[1]<<8) | (av[2]<<16) | (av[3]<<24);
        unsigned hi = av[4] | (av[5]<<8) | (av[6]<<16) | (av[7]<<24);
        __stcg((uint2*)&g_alpha[0][p0], make_uint2(lo, hi));

        float v[7] = {s0,s1,s2,cnt,t0,t1,t2};
        #pragma unroll
        for (int j = 0; j < 7; j++)
            #pragma unroll
            for (int o = 16; o; o >>= 1)
                v[j] += __shfl_down_sync(0xFFFFFFFFu, v[j], o);
        if (lane == 0)
            #pragma unroll
            for (int j = 0; j < 7; j++) s_f[j*8 + warp] = v[j];
        __syncthreads();
        if (t == 0) {
            float r7[7];
            #pragma unroll
            for (int j = 0; j < 7; j++) {
                float acc = s_f[j*8];
                #pragma unroll
                for (int i = 1; i < 8; i++) acc += s_f[j*8 + i];
                r7[j] = acc;
            }
            atomicAdd(&g_fgsum[0][b][0], (double)r7[0]);
            atomicAdd(&g_fgsum[0][b][1], (double)r7[1]);
            atomicAdd(&g_fgsum[0][b][2], (double)r7[2]);
            atomicAdd(&g_fgcnt[0][b], r7[3]);
            atomicAdd(&g_tot[b][0], (double)r7[4]);
            atomicAdd(&g_tot[b][1], (double)r7[5]);
            atomicAdd(&g_tot[b][2], (double)r7[6]);
        }
    }
    bar += GRID; gridbar(bar);

    // ======== phase 3: 5 ICM iterations ========
    uint4 ia = *(const uint4*)&g_img[p0];
    uint4 ib = *(const uint4*)&g_img[p0 + 4];
    const unsigned px[8] = {ia.x,ia.y,ia.z,ia.w,ib.x,ib.y,ib.z,ib.w};

    for (int k = 0; k < 5; k++) {
        const bool last = (k == 4);
        if (t == 0) {
            float cntf = __ldcg(&g_fgcnt[k][b]);
            float fgc = __fadd_rn(cntf, 1e-6f);
            float bgc = __fadd_rn(__fsub_rn((float)HW, cntf), 1e-6f);
            double fs0 = __ldcg(&g_fgsum[k][b][0]);
            double fs1 = __ldcg(&g_fgsum[k][b][1]);
            double fs2 = __ldcg(&g_fgsum[k][b][2]);
            double tt0 = __ldcg(&g_tot[b][0]);
            double tt1 = __ldcg(&g_tot[b][1]);
            double tt2 = __ldcg(&g_tot[b][2]);
            s_means[0] = __fdiv_rn((float)fs0, fgc);
            s_means[1] = __fdiv_rn((float)fs1, fgc);
            s_means[2] = __fdiv_rn((float)fs2, fgc);
            s_means[3] = __fdiv_rn((float)(tt0 - fs0), bgc);
            s_means[4] = __fdiv_rn((float)(tt1 - fs1), bgc);
            s_means[5] = __fdiv_rn((float)(tt2 - fs2), bgc);
        }
        __syncthreads();
        float fm0=s_means[0], fm1=s_means[1], fm2=s_means[2];
        float bm0=s_means[3], bm1=s_means[4], bm2=s_means[5];

        const unsigned char* __restrict__ A  = g_alpha[k & 1];
        unsigned char* __restrict__       An = g_alpha[(k + 1) & 1];

        uint2 selfv = __ldcg((const uint2*)(A + p0));
        uint2 upv   = (y > 0)   ? __ldcg((const uint2*)(A + p0 - WW)) : selfv;
        uint2 dnv   = (y < 511) ? __ldcg((const uint2*)(A + p0 + WW)) : selfv;
        int sb[10];
        sb[1] =  selfv.x        & 255; sb[2] = (selfv.x >> 8)  & 255;
        sb[3] = (selfv.x >> 16) & 255; sb[4] = (selfv.x >> 24) & 255;
        sb[5] =  selfv.y        & 255; sb[6] = (selfv.y >> 8)  & 255;
        sb[7] = (selfv.y >> 16) & 255; sb[8] = (selfv.y >> 24) & 255;
        sb[0] = (x0 > 0)   ? (int)__ldcg(A + p0 - 1) : sb[1];
        sb[9] = (x0 < 504) ? (int)__ldcg(A + p0 + 8) : sb[8];
        int ub[8] = { (int)(upv.x&255), (int)((upv.x>>8)&255), (int)((upv.x>>16)&255), (int)((upv.x>>24)&255),
                      (int)(upv.y&255), (int)((upv.y>>8)&255), (int)((upv.y>>16)&255), (int)((upv.y>>24)&255) };
        int db[8] = { (int)(dnv.x&255), (int)((dnv.x>>8)&255), (int)((dnv.x>>16)&255), (int)((dnv.x>>24)&255),
                      (int)(dnv.y&255), (int)((dnv.y>>8)&255), (int)((dnv.y>>16)&255), (int)((dnv.y>>24)&255) };

        unsigned newa[8]; float outv[8];
        float s0=0, s1=0, s2=0, cnt=0;
        #pragma unroll
        for (int j = 0; j < 8; j++) {
            float i0 = (float)( px[j]        & 255);
            float i1 = (float)((px[j] >> 8)  & 255);
            float i2 = (float)((px[j] >> 16) & 255);
            float nb = __fmul_rn((float)(ub[j] + db[j] + sb[j] + sb[j + 2]), 0.25f);

            float d0=__fsub_rn(i0,fm0), d1=__fsub_rn(i1,fm1), d2=__fsub_rn(i2,fm2);
            float dfg=__fadd_rn(__fadd_rn(__fmul_rn(d0,d0),__fmul_rn(d1,d1)),__fmul_rn(d2,d2));
            float e0=__fsub_rn(i0,bm0), e1=__fsub_rn(i1,bm1), e2=__fsub_rn(i2,bm2);
            float dbg=__fadd_rn(__fadd_rn(__fmul_rn(e0,e0),__fmul_rn(e1,e1)),__fmul_rn(e2,e2));
            float pw = __fmul_rn(50.0f, __fsub_rn(__fmul_rn(2.0f, nb), 1.0f));
            float score = __fadd_rn(__fsub_rn(dbg, dfg), pw);

            unsigned a = fixedv[j] ? (unsigned)fixval[j] : (score > 0.0f ? 1u : 0u);
            newa[j] = a;
            if (!last) {
                float af = (float)a;
                s0 += i0*af; s1 += i1*af; s2 += i2*af; cnt += af;
            } else {
                outv[j] = (float)a;
            }
        }
        unsigned lo = newa[0] | (newa[1]<<8) | (newa[2]<<16) | (newa[3]<<24);
        unsigned hi = newa[4] | (newa[5]<<8) | (newa[6]<<16) | (newa[7]<<24);
        __stcg((uint2*)(An + p0), make_uint2(lo, hi));

        if (last) {
            *(float4*)(out + p0)     = make_float4(outv[0],outv[1],outv[2],outv[3]);
            *(float4*)(out + p0 + 4) = make_float4(outv[4],outv[5],outv[6],outv[7]);
        } else {
            float v[4] = {s0, s1, s2, cnt};
            #pragma unroll
            for (int j = 0; j < 4; j++)
                #pragma unroll
                for (int o = 16; o; o >>= 1)
                    v[j] += __shfl_down_sync(0xFFFFFFFFu, v[j], o);
            if (lane == 0)
                #pragma unroll
                for (int j = 0; j < 4; j++) s_f[j*8 + warp] = v[j];
            __syncthreads();
            if (t == 0) {
                float r4[4];
                #pragma unroll
                for (int j = 0; j < 4; j++) {
                    float acc = s_f[j*8];
                    #pragma unroll
                    for (int i = 1; i < 8; i++) acc += s_f[j*8 + i];
                    r4[j] = acc;
                }
                atomicAdd(&g_fgsum[k+1][b][0], (double)r4[0]);
                atomicAdd(&g_fgsum[k+1][b][1], (double)r4[1]);
                atomicAdd(&g_fgsum[k+1][b][2], (double)r4[2]);
                atomicAdd(&g_fgcnt[k+1][b], r4[3]);
            }
            bar += GRID; gridbar(bar);
        }
    }
}

extern "C" void kernel_launch(void* const* d_in, const int* in_sizes, int n_in,
                              void* d_out, int out_size) {
    const float* feat = (const float*)d_in[0];
    const int*   mask = (const int*)d_in[1];
    float*       out  = (float*)d_out;

    k_init<<<1, 64>>>();
    k_fused<<<GRID, TPB>>>(feat, mask, out);
}